// round 3
// baseline (speedup 1.0000x reference)
#include <cuda_runtime.h>
#include <stdint.h>

#define NUM_NODES 50000
#define NUM_EDGES 600000
#define DD 128
#define FF 128

#define BM 64
#define BN 128
#define BK 16
#define TM 8
#define TN 8
#define AS_STRIDE 68   // BM + 4 pad: kills transpose-store bank conflicts

// Scratch: aggregated messages [NUM_NODES, D]
__device__ float g_agg[NUM_NODES * DD];
// Flag: 1 if index arrays are int64, 0 if int32
__device__ int g_is64;

// ---------------------------------------------------------------------------
// Detect index dtype (int64 vs int32) from the data pattern. Deterministic.
// ---------------------------------------------------------------------------
__global__ void detect_kernel(const int* __restrict__ w) {
    __shared__ int cnt;
    if (threadIdx.x == 0) cnt = 0;
    __syncthreads();
    int nz = 0;
    for (int i = threadIdx.x * 2 + 1; i < 2048; i += 2 * blockDim.x)
        nz += (w[i] != 0);
    atomicAdd(&cnt, nz);
    __syncthreads();
    if (threadIdx.x == 0) g_is64 = (cnt < 512) ? 1 : 0;
}

// ---------------------------------------------------------------------------
// Zero the aggregation buffer
// ---------------------------------------------------------------------------
__global__ void zero_kernel() {
    int i = blockIdx.x * blockDim.x + threadIdx.x;
    float4 z = make_float4(0.f, 0.f, 0.f, 0.f);
    if (i < NUM_NODES * DD / 4) reinterpret_cast<float4*>(g_agg)[i] = z;
}

// ---------------------------------------------------------------------------
// Scatter-add: one warp per edge, red.global.add.v4.f32 (L2-resident)
// ---------------------------------------------------------------------------
__global__ void scatter_kernel(const float* __restrict__ x,
                               const void* __restrict__ src,
                               const void* __restrict__ tgt) {
    int e = (blockIdx.x * blockDim.x + threadIdx.x) >> 5;
    if (e >= NUM_EDGES) return;
    int lane = threadIdx.x & 31;

    long long s, t;
    if (g_is64) {
        s = reinterpret_cast<const long long*>(src)[e];
        t = reinterpret_cast<const long long*>(tgt)[e];
    } else {
        s = reinterpret_cast<const int*>(src)[e];
        t = reinterpret_cast<const int*>(tgt)[e];
    }

    float4 v = reinterpret_cast<const float4*>(x + s * DD)[lane];
    float* dst = g_agg + t * DD + lane * 4;
    asm volatile("red.global.add.v4.f32 [%0], {%1, %2, %3, %4};"
                 :: "l"(dst), "f"(v.x), "f"(v.y), "f"(v.z), "f"(v.w)
                 : "memory");
}

// ---------------------------------------------------------------------------
// GEMM: out[n,j] = sum_k H[n,k] W[k,j] + b[j], H = [agg | x], K=256.
// Double-buffered SGEMM: BM=64 x BN=128, BK=16, 128 threads, 8x8 micro-tile.
// K-chunks 0-7 read g_agg, 8-15 read node_x (no concat staging).
// smem ~25KB static, regs capped at 128 -> 4 CTAs/SM (16 warps).
// ---------------------------------------------------------------------------
__device__ __forceinline__ void load_tiles(
    const float* __restrict__ hbase,  // chunk base (g_agg+k0 or x+k0-128)
    const float* __restrict__ W, int k0,
    float* __restrict__ As, float* __restrict__ Bs,
    int tid, int nbase)
{
    // A: 64 rows x 16 cols -> transposed As[k][m]
    int ar = tid >> 2;       // 0..31 (rows ar, ar+32)
    int aq = tid & 3;        // col quad
    #pragma unroll
    for (int h = 0; h < 2; h++) {
        int r = ar + h * 32;
        int node = nbase + r;
        float4 v = make_float4(0.f, 0.f, 0.f, 0.f);
        if (node < NUM_NODES)
            v = *reinterpret_cast<const float4*>(hbase + (long long)node * DD + aq * 4);
        As[(aq * 4 + 0) * AS_STRIDE + r] = v.x;
        As[(aq * 4 + 1) * AS_STRIDE + r] = v.y;
        As[(aq * 4 + 2) * AS_STRIDE + r] = v.z;
        As[(aq * 4 + 3) * AS_STRIDE + r] = v.w;
    }
    // B: W rows k0..k0+15, 128 cols, natural layout, fully coalesced
    int bc = tid & 31;       // float4 column
    int br = tid >> 5;       // 0..3
    #pragma unroll
    for (int h = 0; h < 4; h++) {
        int kr = br + h * 4;
        float4 v = *reinterpret_cast<const float4*>(W + (k0 + kr) * FF + bc * 4);
        *reinterpret_cast<float4*>(Bs + kr * BN + bc * 4) = v;
    }
}

__global__ void __launch_bounds__(128, 4)
gemm_kernel(const float* __restrict__ x, const float* __restrict__ W,
            const float* __restrict__ b, float* __restrict__ out) {
    __shared__ float As[2][BK * AS_STRIDE];
    __shared__ float Bs[2][BK * BN];

    int tid = threadIdx.x;
    int nbase = blockIdx.x * BM;
    int m_idx = tid >> 4;    // 0..7
    int n_idx = tid & 15;    // 0..15

    float acc[TM][TN];
    #pragma unroll
    for (int i = 0; i < TM; i++)
        #pragma unroll
        for (int j = 0; j < TN; j++) acc[i][j] = 0.f;

    // chunk 0
    load_tiles(g_agg, W, 0, As[0], Bs[0], tid, nbase);
    __syncthreads();

    #pragma unroll
    for (int c = 0; c < 16; c++) {
        if (c + 1 < 16) {
            int k0 = (c + 1) * BK;
            const float* hbase = (k0 < 128) ? (g_agg + k0) : (x + k0 - 128);
            load_tiles(hbase, W, k0, As[(c + 1) & 1], Bs[(c + 1) & 1], tid, nbase);
        }
        const float* Ac = As[c & 1];
        const float* Bc = Bs[c & 1];
        #pragma unroll
        for (int k = 0; k < BK; k++) {
            float4 a0 = *reinterpret_cast<const float4*>(Ac + k * AS_STRIDE + m_idx * 8);
            float4 a1 = *reinterpret_cast<const float4*>(Ac + k * AS_STRIDE + m_idx * 8 + 4);
            float4 b0 = *reinterpret_cast<const float4*>(Bc + k * BN + n_idx * 8);
            float4 b1 = *reinterpret_cast<const float4*>(Bc + k * BN + n_idx * 8 + 4);
            float av[TM] = {a0.x, a0.y, a0.z, a0.w, a1.x, a1.y, a1.z, a1.w};
            float bv[TN] = {b0.x, b0.y, b0.z, b0.w, b1.x, b1.y, b1.z, b1.w};
            #pragma unroll
            for (int i = 0; i < TM; i++)
                #pragma unroll
                for (int j = 0; j < TN; j++)
                    acc[i][j] += av[i] * bv[j];
        }
        __syncthreads();
    }

    float4 bv0 = *reinterpret_cast<const float4*>(b + n_idx * 8);
    float4 bv1 = *reinterpret_cast<const float4*>(b + n_idx * 8 + 4);
    #pragma unroll
    for (int i = 0; i < TM; i++) {
        int node = nbase + m_idx * 8 + i;
        if (node < NUM_NODES) {
            float4 o0 = make_float4(acc[i][0] + bv0.x, acc[i][1] + bv0.y,
                                    acc[i][2] + bv0.z, acc[i][3] + bv0.w);
            float4 o1 = make_float4(acc[i][4] + bv1.x, acc[i][5] + bv1.y,
                                    acc[i][6] + bv1.z, acc[i][7] + bv1.w);
            float* orow = out + (long long)node * FF + n_idx * 8;
            *reinterpret_cast<float4*>(orow) = o0;
            *reinterpret_cast<float4*>(orow + 4) = o1;
        }
    }
}

extern "C" void kernel_launch(void* const* d_in, const int* in_sizes, int n_in,
                              void* d_out, int out_size) {
    const float* node_x = (const float*)d_in[0];
    const void*  sources = d_in[1];
    const void*  targets = d_in[2];
    const float* W = (const float*)d_in[3];
    const float* b = (const float*)d_in[4];
    float* out = (float*)d_out;

    detect_kernel<<<1, 256>>>((const int*)sources);
    zero_kernel<<<(NUM_NODES * DD / 4 + 255) / 256, 256>>>();

    long long threads = (long long)NUM_EDGES * 32;
    int blocks = (int)((threads + 255) / 256);
    scatter_kernel<<<blocks, 256>>>(node_x, sources, targets);

    gemm_kernel<<<(NUM_NODES + BM - 1) / BM, 128>>>(node_x, W, b, out);
}

// round 5
// speedup vs baseline: 1.3311x; 1.3311x over previous
#include <cuda_runtime.h>
#include <stdint.h>

#define NUM_NODES 50000
#define NUM_EDGES 600000
#define DD 128
#define FF 128

#define BK 16
#define A_STR 20    // 16 k + 4 pad -> conflict-free frag loads
#define B_STR 136   // 128 n + 8 pad -> conflict-free frag loads

// smem layout (uint32 units) inside one dynamic block
#define AH_OFF 0
#define AL_OFF (AH_OFF + 2 * 128 * A_STR)
#define BH_OFF (AL_OFF + 2 * 128 * A_STR)
#define BL_OFF (BH_OFF + 2 * BK * B_STR)
#define SMEM_WORDS (BL_OFF + 2 * BK * B_STR)
#define SMEM_BYTES (SMEM_WORDS * 4)   // 75776

// Scratch: aggregated messages [NUM_NODES, D]
__device__ float g_agg[NUM_NODES * DD];
__device__ int g_is64;

// ---------------------------------------------------------------------------
// Detect index dtype (int64 vs int32) from data pattern. Deterministic.
// ---------------------------------------------------------------------------
__global__ void detect_kernel(const int* __restrict__ w) {
    __shared__ int cnt;
    if (threadIdx.x == 0) cnt = 0;
    __syncthreads();
    int nz = 0;
    for (int i = threadIdx.x * 2 + 1; i < 2048; i += 2 * blockDim.x)
        nz += (w[i] != 0);
    atomicAdd(&cnt, nz);
    __syncthreads();
    if (threadIdx.x == 0) g_is64 = (cnt < 512) ? 1 : 0;
}

__global__ void zero_kernel() {
    int i = blockIdx.x * blockDim.x + threadIdx.x;
    float4 z = make_float4(0.f, 0.f, 0.f, 0.f);
    if (i < NUM_NODES * DD / 4) reinterpret_cast<float4*>(g_agg)[i] = z;
}

// ---------------------------------------------------------------------------
// Scatter-add: one warp per edge, red.global.add.v4.f32 (L2-resident)
// ---------------------------------------------------------------------------
__global__ void scatter_kernel(const float* __restrict__ x,
                               const void* __restrict__ src,
                               const void* __restrict__ tgt) {
    int e = (blockIdx.x * blockDim.x + threadIdx.x) >> 5;
    if (e >= NUM_EDGES) return;
    int lane = threadIdx.x & 31;

    long long s, t;
    if (g_is64) {
        s = reinterpret_cast<const long long*>(src)[e];
        t = reinterpret_cast<const long long*>(tgt)[e];
    } else {
        s = reinterpret_cast<const int*>(src)[e];
        t = reinterpret_cast<const int*>(tgt)[e];
    }

    float4 v = reinterpret_cast<const float4*>(x + s * DD)[lane];
    float* dst = g_agg + t * DD + lane * 4;
    asm volatile("red.global.add.v4.f32 [%0], {%1, %2, %3, %4};"
                 :: "l"(dst), "f"(v.x), "f"(v.y), "f"(v.z), "f"(v.w)
                 : "memory");
}

// ---------------------------------------------------------------------------
// Tensor-core GEMM via 3xTF32: out = [agg|x] @ W + b,  M=50000, N=128, K=256.
// CTA 128x128, 8 warps (4m x 2n), warp tile 32x64, mma.m16n8k8 tf32.
// a*b ~= hi_a*hi_b + hi_a*lo_b + lo_a*hi_b  (fp32-grade accuracy)
// ---------------------------------------------------------------------------
__device__ __forceinline__ void cvt_split(float f, uint32_t& h, uint32_t& l) {
    asm("cvt.rna.tf32.f32 %0, %1;" : "=r"(h) : "f"(f));
    float r = f - __uint_as_float(h);
    asm("cvt.rna.tf32.f32 %0, %1;" : "=r"(l) : "f"(r));
}

__device__ __forceinline__ void mma_tf32(float* d, const uint32_t* a,
                                         uint32_t b0, uint32_t b1) {
    asm volatile(
        "mma.sync.aligned.m16n8k8.row.col.f32.tf32.tf32.f32 "
        "{%0,%1,%2,%3}, {%4,%5,%6,%7}, {%8,%9}, {%0,%1,%2,%3};"
        : "+f"(d[0]), "+f"(d[1]), "+f"(d[2]), "+f"(d[3])
        : "r"(a[0]), "r"(a[1]), "r"(a[2]), "r"(a[3]), "r"(b0), "r"(b1));
}

__device__ __forceinline__ void load_chunk(
    const float* __restrict__ hbase, const float* __restrict__ W, int k0,
    uint32_t* __restrict__ Ah, uint32_t* __restrict__ Al,
    uint32_t* __restrict__ Bh, uint32_t* __restrict__ Bl,
    int tid, int nbase)
{
    // A: 128 rows x 16 k (hbase already offset by k0 into the 256-wide H)
    #pragma unroll
    for (int i = 0; i < 2; i++) {
        int idx = tid + i * 256;          // 0..511
        int r = idx >> 2, q = idx & 3;
        int node = nbase + r;
        float4 v = make_float4(0.f, 0.f, 0.f, 0.f);
        if (node < NUM_NODES)
            v = *reinterpret_cast<const float4*>(hbase + (long long)node * DD + q * 4);
        uint32_t h0,l0,h1,l1,h2,l2,h3,l3;
        cvt_split(v.x, h0, l0); cvt_split(v.y, h1, l1);
        cvt_split(v.z, h2, l2); cvt_split(v.w, h3, l3);
        int o = r * A_STR + q * 4;
        Ah[o] = h0; Ah[o+1] = h1; Ah[o+2] = h2; Ah[o+3] = h3;
        Al[o] = l0; Al[o+1] = l1; Al[o+2] = l2; Al[o+3] = l3;
    }
    // B: W rows k0..k0+15 x 128 cols, coalesced float4
    #pragma unroll
    for (int i = 0; i < 2; i++) {
        int idx = tid + i * 256;          // 0..511
        int r = idx >> 5, q = idx & 31;
        float4 v = *reinterpret_cast<const float4*>(W + (k0 + r) * FF + q * 4);
        uint32_t h0,l0,h1,l1,h2,l2,h3,l3;
        cvt_split(v.x, h0, l0); cvt_split(v.y, h1, l1);
        cvt_split(v.z, h2, l2); cvt_split(v.w, h3, l3);
        int o = r * B_STR + q * 4;
        Bh[o] = h0; Bh[o+1] = h1; Bh[o+2] = h2; Bh[o+3] = h3;
        Bl[o] = l0; Bl[o+1] = l1; Bl[o+2] = l2; Bl[o+3] = l3;
    }
}

__global__ void __launch_bounds__(256, 2)
gemm_kernel(const float* __restrict__ x, const float* __restrict__ W,
            const float* __restrict__ b, float* __restrict__ out) {
    extern __shared__ uint32_t smem[];
    uint32_t* AhB = smem + AH_OFF;   // [2][128*A_STR]
    uint32_t* AlB = smem + AL_OFF;
    uint32_t* BhB = smem + BH_OFF;   // [2][BK*B_STR]
    uint32_t* BlB = smem + BL_OFF;

    int tid = threadIdx.x;
    int lane = tid & 31, wid = tid >> 5;
    int gid = lane >> 2, tig = lane & 3;
    int wm = wid & 3;          // 0..3 -> 32-row slab
    int wn = wid >> 2;         // 0..1 -> 64-col slab
    int nbase = blockIdx.x * 128;

    float acc[2][8][4];
    #pragma unroll
    for (int mt = 0; mt < 2; mt++)
        #pragma unroll
        for (int nt = 0; nt < 8; nt++)
            #pragma unroll
            for (int f = 0; f < 4; f++) acc[mt][nt][f] = 0.f;

    load_chunk(g_agg, W, 0, AhB, AlB, BhB, BlB, tid, nbase);
    __syncthreads();

    for (int c = 0; c < 16; c++) {
        if (c + 1 < 16) {
            int k0 = (c + 1) * BK;
            const float* hbase = (k0 < 128) ? (g_agg + k0) : (x + k0 - 128);
            int nb = (c + 1) & 1;
            load_chunk(hbase, W, k0,
                       AhB + nb * 128 * A_STR, AlB + nb * 128 * A_STR,
                       BhB + nb * BK * B_STR,  BlB + nb * BK * B_STR,
                       tid, nbase);
        }
        int cb = c & 1;
        const uint32_t* cAh = AhB + cb * 128 * A_STR;
        const uint32_t* cAl = AlB + cb * 128 * A_STR;
        const uint32_t* cBh = BhB + cb * BK * B_STR;
        const uint32_t* cBl = BlB + cb * BK * B_STR;

        #pragma unroll
        for (int ks = 0; ks < 2; ks++) {
            uint32_t ah[2][4], al[2][4];
            #pragma unroll
            for (int mt = 0; mt < 2; mt++) {
                int m = wm * 32 + mt * 16 + gid;
                int ro = m * A_STR + ks * 8 + tig;
                ah[mt][0] = cAh[ro];
                ah[mt][1] = cAh[ro + 8 * A_STR];
                ah[mt][2] = cAh[ro + 4];
                ah[mt][3] = cAh[ro + 8 * A_STR + 4];
                al[mt][0] = cAl[ro];
                al[mt][1] = cAl[ro + 8 * A_STR];
                al[mt][2] = cAl[ro + 4];
                al[mt][3] = cAl[ro + 8 * A_STR + 4];
            }
            #pragma unroll
            for (int nt = 0; nt < 8; nt++) {
                int n = wn * 64 + nt * 8 + gid;
                int bo = (ks * 8 + tig) * B_STR + n;
                uint32_t b0h = cBh[bo], b1h = cBh[bo + 4 * B_STR];
                uint32_t b0l = cBl[bo], b1l = cBl[bo + 4 * B_STR];
                #pragma unroll
                for (int mt = 0; mt < 2; mt++) {
                    mma_tf32(acc[mt][nt], ah[mt], b0h, b1h);  // hi*hi
                    mma_tf32(acc[mt][nt], ah[mt], b0l, b1l);  // hi*lo
                    mma_tf32(acc[mt][nt], al[mt], b0h, b1h);  // lo*hi
                }
            }
        }
        __syncthreads();
    }

    // Epilogue: add bias, write float2 pairs
    #pragma unroll
    for (int mt = 0; mt < 2; mt++) {
        #pragma unroll
        for (int nt = 0; nt < 8; nt++) {
            int col = wn * 64 + nt * 8 + tig * 2;
            float2 bb = *reinterpret_cast<const float2*>(b + col);
            int row0 = nbase + wm * 32 + mt * 16 + gid;
            if (row0 < NUM_NODES) {
                float2 o = make_float2(acc[mt][nt][0] + bb.x, acc[mt][nt][1] + bb.y);
                *reinterpret_cast<float2*>(out + (long long)row0 * FF + col) = o;
            }
            int row1 = row0 + 8;
            if (row1 < NUM_NODES) {
                float2 o = make_float2(acc[mt][nt][2] + bb.x, acc[mt][nt][3] + bb.y);
                *reinterpret_cast<float2*>(out + (long long)row1 * FF + col) = o;
            }
        }
    }
}

extern "C" void kernel_launch(void* const* d_in, const int* in_sizes, int n_in,
                              void* d_out, int out_size) {
    const float* node_x = (const float*)d_in[0];
    const void*  sources = d_in[1];
    const void*  targets = d_in[2];
    const float* W = (const float*)d_in[3];
    const float* b = (const float*)d_in[4];
    float* out = (float*)d_out;

    cudaFuncSetAttribute(gemm_kernel,
                         cudaFuncAttributeMaxDynamicSharedMemorySize, SMEM_BYTES);

    detect_kernel<<<1, 256>>>((const int*)sources);
    zero_kernel<<<(NUM_NODES * DD / 4 + 255) / 256, 256>>>();

    long long threads = (long long)NUM_EDGES * 32;
    int blocks = (int)((threads + 255) / 256);
    scatter_kernel<<<blocks, 256>>>(node_x, sources, targets);

    gemm_kernel<<<(NUM_NODES + 127) / 128, 256, SMEM_BYTES>>>(node_x, W, b, out);
}